// round 1
// baseline (speedup 1.0000x reference)
#include <cuda_runtime.h>
#include <math.h>

// Problem constants
#define Nn   4096
#define Mm   2048
#define IS   128     // INPUT_SIZE
#define XC   129     // x columns (INPUT_SIZE+1)
#define INDIM 257    // 2*I+1
#define QDIM 32
#define CATP 288     // padded concat width (9*32), cols 257..287 are zero
#define KG   8224    // 257*32, K of the gate GEMM (W part)
#define NT   258     // 257 W tiles + 1 bias tile (BK=32)

// Scratch (static device globals; no runtime allocation)
__device__ float g_cat [Nn * CATP];   // concat(x,h) padded, row-major [4096][288]
__device__ float g_cgT [CATP * Mm];   // cg transposed: [i][m]
__device__ float g_cnT [CATP * Mm];   // cn transposed: [i][m]
__device__ float g_r   [Mm * IS];
__device__ float g_u   [Mm * IS];

typedef unsigned long long ull;

__device__ __forceinline__ void fma2(ull &c, ull a, ull b) {
    asm("fma.rn.f32x2 %0, %1, %2, %0;" : "+l"(c) : "l"(a), "l"(b));
}
__device__ __forceinline__ ull pack2(float x, float y) {
    ull r; asm("mov.b64 %0, {%1, %2};" : "=l"(r) : "f"(x), "f"(y)); return r;
}
__device__ __forceinline__ float2 unpack2(ull v) {
    float2 f; asm("mov.b64 {%0, %1}, %2;" : "=f"(f.x), "=f"(f.y) : "l"(v)); return f;
}
__device__ __forceinline__ float sigmoidf_(float v) {
    return 1.0f / (1.0f + expf(-v));
}

// ---------------------------------------------------------------------------
// Pack concat(x,h) -> g_cat [4096][288], zero padded cols
// ---------------------------------------------------------------------------
__global__ void k_pack_cat(const float* __restrict__ x, const float* __restrict__ h) {
    int idx = blockIdx.x * 256 + threadIdx.x;
    if (idx >= Nn * CATP) return;
    int row = idx / CATP;
    int c   = idx - row * CATP;
    float v = 0.0f;
    if (c < XC)        v = x[row * XC + c];
    else if (c < INDIM) v = h[row * IS + (c - XC)];
    g_cat[idx] = v;
}

// ---------------------------------------------------------------------------
// GEMM1: cgT[j][m] = sum_k adj[nodes[m]][k] * cat[k][j]
// grid (9, 16): n0 = bx*32 (288 cols), m0 = by*128 ; 256 threads
// ---------------------------------------------------------------------------
__global__ __launch_bounds__(256) void k_gemm1(const float* __restrict__ adj,
                                               const int* __restrict__ nodes) {
    __shared__ float As[32][136];   // [kk][m], padded rows
    __shared__ float Bs[32][32];    // [kk][n]
    __shared__ int rows[128];

    int t  = threadIdx.x;
    int m0 = blockIdx.y * 128;
    int n0 = blockIdx.x * 32;
    if (t < 128) rows[t] = nodes[m0 + t];
    __syncthreads();

    int w = t >> 5, lane = t & 31;
    int tx = t & 7, ty = t >> 3;   // tx: 8 col-groups *4, ty: 32 row-groups *4

    ull acc[4][2];
#pragma unroll
    for (int r = 0; r < 4; r++) { acc[r][0] = 0ULL; acc[r][1] = 0ULL; }

    for (int k0 = 0; k0 < Nn; k0 += 32) {
        // A tile: warp w loads k-cols [4w,4w+4), lane = row (conflict-free STS)
#pragma unroll
        for (int p = 0; p < 4; p++) {
            int row = lane + 32 * p;
            const float4 v = *(const float4*)&adj[(size_t)rows[row] * Nn + k0 + w * 4];
            As[w * 4 + 0][row] = v.x;
            As[w * 4 + 1][row] = v.y;
            As[w * 4 + 2][row] = v.z;
            As[w * 4 + 3][row] = v.w;
        }
        // B tile: 32x32 from g_cat (coalesced)
        {
            int kk = t >> 3, c4 = t & 7;
            *(float4*)&Bs[kk][c4 * 4] =
                *(const float4*)&g_cat[(size_t)(k0 + kk) * CATP + n0 + c4 * 4];
        }
        __syncthreads();

#pragma unroll
        for (int kk = 0; kk < 32; kk++) {
            float4 a4 = *(const float4*)&As[kk][ty * 4];
            ulonglong2 bb = *(const ulonglong2*)&Bs[kk][tx * 4];
            float av[4] = {a4.x, a4.y, a4.z, a4.w};
#pragma unroll
            for (int r = 0; r < 4; r++) {
                ull ar = pack2(av[r], av[r]);
                fma2(acc[r][0], ar, bb.x);
                fma2(acc[r][1], ar, bb.y);
            }
        }
        __syncthreads();
    }

    // write transposed: g_cgT[col][m]
#pragma unroll
    for (int r = 0; r < 4; r++) {
        float2 c0 = unpack2(acc[r][0]);
        float2 c1 = unpack2(acc[r][1]);
        int m = m0 + ty * 4 + r;
        int c = n0 + tx * 4;
        g_cgT[(size_t)(c + 0) * Mm + m] = c0.x;
        g_cgT[(size_t)(c + 1) * Mm + m] = c0.y;
        g_cgT[(size_t)(c + 2) * Mm + m] = c1.x;
        g_cgT[(size_t)(c + 3) * Mm + m] = c1.y;
    }
}

// ---------------------------------------------------------------------------
// Gates GEMM: r,u together.  out[m,o] = Z[m,:] @ Wflat[:,o] + q@b
// Z[m, d*257+i] = q[m,d]*cg[m,i], built per-tile in smem.
// grid (2, 64): n0 = bx*64, m0 = by*32 ; 256 threads
// ---------------------------------------------------------------------------
__global__ __launch_bounds__(256) void k_gates(const float* __restrict__ q,
                                               const float* __restrict__ Wr,
                                               const float* __restrict__ br,
                                               const float* __restrict__ Wu,
                                               const float* __restrict__ bu) {
    __shared__ float Zs[32][34];
    __shared__ float Wrs[32][64];
    __shared__ float Wus[32][64];
    __shared__ float qs[32][33];

    int t  = threadIdx.x;
    int m0 = blockIdx.y * 32;
    int n0 = blockIdx.x * 64;

#pragma unroll
    for (int p = 0; p < 4; p++) {
        int e = t + 256 * p;
        int m = e >> 5, d = e & 31;
        qs[m][d] = q[(size_t)(m0 + m) * QDIM + d];
    }
    __syncthreads();

    int tx = t & 15, ty = t >> 4;   // tx: 16 col-groups *4, ty: 16 row-groups *2

    ull accr[2][2], accu[2][2];
#pragma unroll
    for (int r = 0; r < 2; r++) {
        accr[r][0] = accr[r][1] = 0ULL;
        accu[r][0] = accu[r][1] = 0ULL;
    }

    for (int tile = 0; tile < NT; tile++) {
        int k0 = tile * 32;
        // Z tile: 32kk x 32m, 4 elems/thread, coalesced read of g_cgT
#pragma unroll
        for (int p = 0; p < 4; p++) {
            int e = t + 256 * p;
            int m = e & 31, kk = e >> 5;
            int k = k0 + kk;
            float v;
            if (tile < 257) {
                int d = k / INDIM;
                int i = k - d * INDIM;
                v = qs[m][d] * g_cgT[(size_t)i * Mm + m0 + m];
            } else {
                v = qs[m][k - KG];
            }
            Zs[kk][m] = v;
        }
        // W tiles (both gates), coalesced float4
#pragma unroll
        for (int p = 0; p < 2; p++) {
            int e = t + 256 * p;
            int kk = e >> 4, c4 = e & 15;
            const float *sR, *sU;
            if (tile < 257) {
                sR = &Wr[(size_t)(k0 + kk) * IS + n0 + c4 * 4];
                sU = &Wu[(size_t)(k0 + kk) * IS + n0 + c4 * 4];
            } else {
                sR = &br[(size_t)kk * IS + n0 + c4 * 4];
                sU = &bu[(size_t)kk * IS + n0 + c4 * 4];
            }
            *(float4*)&Wrs[kk][c4 * 4] = *(const float4*)sR;
            *(float4*)&Wus[kk][c4 * 4] = *(const float4*)sU;
        }
        __syncthreads();

#pragma unroll
        for (int kk = 0; kk < 32; kk++) {
            float2 a2 = *(const float2*)&Zs[kk][ty * 2];
            ulonglong2 brr = *(const ulonglong2*)&Wrs[kk][tx * 4];
            ulonglong2 buu = *(const ulonglong2*)&Wus[kk][tx * 4];
            ull a0 = pack2(a2.x, a2.x);
            ull a1 = pack2(a2.y, a2.y);
            fma2(accr[0][0], a0, brr.x); fma2(accr[0][1], a0, brr.y);
            fma2(accr[1][0], a1, brr.x); fma2(accr[1][1], a1, brr.y);
            fma2(accu[0][0], a0, buu.x); fma2(accu[0][1], a0, buu.y);
            fma2(accu[1][0], a1, buu.x); fma2(accu[1][1], a1, buu.y);
        }
        __syncthreads();
    }

#pragma unroll
    for (int r = 0; r < 2; r++) {
        int m = m0 + ty * 2 + r;
        float2 r0 = unpack2(accr[r][0]), r1 = unpack2(accr[r][1]);
        float2 u0 = unpack2(accu[r][0]), u1 = unpack2(accu[r][1]);
        float vr[4] = {r0.x, r0.y, r1.x, r1.y};
        float vu[4] = {u0.x, u0.y, u1.x, u1.y};
#pragma unroll
        for (int c = 0; c < 4; c++) {
            int col = n0 + tx * 4 + c;
            g_r[(size_t)m * IS + col] = sigmoidf_(vr[c]);
            g_u[(size_t)m * IS + col] = sigmoidf_(vu[c]);
        }
    }
}

// ---------------------------------------------------------------------------
// Pack cnT[i][m]: [x[nm], r*h[nm]] transposed
// ---------------------------------------------------------------------------
__global__ void k_pack_cn(const float* __restrict__ x, const float* __restrict__ h,
                          const int* __restrict__ nodes) {
    int idx = blockIdx.x * 256 + threadIdx.x;
    if (idx >= CATP * Mm) return;
    int i = idx / Mm;
    int m = idx - i * Mm;
    float v = 0.0f;
    if (i < XC) {
        v = x[(size_t)nodes[m] * XC + i];
    } else if (i < INDIM) {
        int j = i - XC;
        v = g_r[(size_t)m * IS + j] * h[(size_t)nodes[m] * IS + j];
    }
    g_cnT[idx] = v;
}

// ---------------------------------------------------------------------------
// Candidate gate + final combine
// grid (2, 64); 256 threads. Same structure as k_gates, single gate.
// ---------------------------------------------------------------------------
__global__ __launch_bounds__(256) void k_final(const float* __restrict__ q,
                                               const float* __restrict__ Wc,
                                               const float* __restrict__ bc,
                                               const float* __restrict__ h,
                                               const int* __restrict__ nodes,
                                               float* __restrict__ out) {
    __shared__ float Zs[32][34];
    __shared__ float Wcs[32][64];
    __shared__ float qs[32][33];

    int t  = threadIdx.x;
    int m0 = blockIdx.y * 32;
    int n0 = blockIdx.x * 64;

#pragma unroll
    for (int p = 0; p < 4; p++) {
        int e = t + 256 * p;
        int m = e >> 5, d = e & 31;
        qs[m][d] = q[(size_t)(m0 + m) * QDIM + d];
    }
    __syncthreads();

    int tx = t & 15, ty = t >> 4;

    ull acc[2][2];
    acc[0][0] = acc[0][1] = acc[1][0] = acc[1][1] = 0ULL;

    for (int tile = 0; tile < NT; tile++) {
        int k0 = tile * 32;
#pragma unroll
        for (int p = 0; p < 4; p++) {
            int e = t + 256 * p;
            int m = e & 31, kk = e >> 5;
            int k = k0 + kk;
            float v;
            if (tile < 257) {
                int d = k / INDIM;
                int i = k - d * INDIM;
                v = qs[m][d] * g_cnT[(size_t)i * Mm + m0 + m];
            } else {
                v = qs[m][k - KG];
            }
            Zs[kk][m] = v;
        }
#pragma unroll
        for (int p = 0; p < 2; p++) {
            int e = t + 256 * p;
            int kk = e >> 4, c4 = e & 15;
            const float* sC = (tile < 257)
                ? &Wc[(size_t)(k0 + kk) * IS + n0 + c4 * 4]
                : &bc[(size_t)kk * IS + n0 + c4 * 4];
            *(float4*)&Wcs[kk][c4 * 4] = *(const float4*)sC;
        }
        __syncthreads();

#pragma unroll
        for (int kk = 0; kk < 32; kk++) {
            float2 a2 = *(const float2*)&Zs[kk][ty * 2];
            ulonglong2 bcc = *(const ulonglong2*)&Wcs[kk][tx * 4];
            ull a0 = pack2(a2.x, a2.x);
            ull a1 = pack2(a2.y, a2.y);
            fma2(acc[0][0], a0, bcc.x); fma2(acc[0][1], a0, bcc.y);
            fma2(acc[1][0], a1, bcc.x); fma2(acc[1][1], a1, bcc.y);
        }
        __syncthreads();
    }

#pragma unroll
    for (int r = 0; r < 2; r++) {
        int m = m0 + ty * 2 + r;
        int nm = nodes[m];
        float2 c0 = unpack2(acc[r][0]), c1 = unpack2(acc[r][1]);
        float v[4] = {c0.x, c0.y, c1.x, c1.y};
#pragma unroll
        for (int c = 0; c < 4; c++) {
            int col = n0 + tx * 4 + c;
            float cand = tanhf(v[c]);
            float uu = g_u[(size_t)m * IS + col];
            float rr = g_r[(size_t)m * IS + col];
            float hv = h[(size_t)nm * IS + col];
            out[(size_t)m * IS + col] = (1.0f - uu) * rr * hv + uu * cand;
        }
    }
}

// ---------------------------------------------------------------------------
// Launch
// Inputs (metadata order): x, h, query_vectors, adj, nodes_ind,
//                          W_u, b_u, W_r, b_r, W_c, b_c
// ---------------------------------------------------------------------------
extern "C" void kernel_launch(void* const* d_in, const int* in_sizes, int n_in,
                              void* d_out, int out_size) {
    const float* x    = (const float*)d_in[0];
    const float* h    = (const float*)d_in[1];
    const float* q    = (const float*)d_in[2];
    const float* adj  = (const float*)d_in[3];
    const int*   nodes= (const int*)  d_in[4];
    const float* Wu   = (const float*)d_in[5];
    const float* bu   = (const float*)d_in[6];
    const float* Wr   = (const float*)d_in[7];
    const float* br   = (const float*)d_in[8];
    const float* Wc   = (const float*)d_in[9];
    const float* bc   = (const float*)d_in[10];
    float* out = (float*)d_out;

    k_pack_cat<<<(Nn * CATP + 255) / 256, 256>>>(x, h);
    k_gemm1<<<dim3(9, 16), 256>>>(adj, nodes);
    k_gates<<<dim3(2, 64), 256>>>(q, Wr, br, Wu, bu);
    k_pack_cn<<<(CATP * Mm + 255) / 256, 256>>>(x, h, nodes);
    k_final<<<dim3(2, 64), 256>>>(q, Wc, bc, h, nodes, out);
}